// round 2
// baseline (speedup 1.0000x reference)
#include <cuda_runtime.h>
#include <math.h>

// ---------------------------------------------------------------------------
// GAT (4 heads x 32) + linear autoencoder head, N=50000, E=800000, C=128.
// Pipeline:
//   k_prep : W_cd = W_enc @ W_dec, b_cd = b_enc @ W_dec + b_dec   (tiny)
//   k1_gat : h = x @ W_gat ; a_src/a_dst per node ; self-loop init of
//            denom (exp term) and agg (p_self * h)                 (GEMM)
//   k_edge : one pass over edges: p = exp(lrelu(a_src[s]+a_dst[d]))
//            red.v4 denom[d] += p ; red.v4 agg[d] += p*h[s]        (scatter)
//   k_tail : x1 = elu(agg/denom + b_gat) ; dec = x1@W_cd + b_cd ;
//            x2 = elu(dec) ; out = x2@W_out + b_out                (2 GEMMs)
// Softmax max-subtraction is skipped (shift-invariant, args bounded ~|9|),
// and normalization is deferred to k_tail, so edges need ONE pass only.
// NOTE: edge_index is int32 on device (JAX downcasts int64 without x64 mode).
// ---------------------------------------------------------------------------

#define MAXN 50176
#define TM 64

__device__ __align__(16) float g_h[MAXN * 128];
__device__ __align__(16) float g_agg[MAXN * 128];
__device__ __align__(16) float g_asrc[MAXN * 4];
__device__ __align__(16) float g_adst[MAXN * 4];
__device__ __align__(16) float g_denom[MAXN * 4];
__device__ __align__(16) float g_Wcd[128 * 128];
__device__ __align__(16) float g_bcd[128];

__device__ __forceinline__ float lrelu(float v) { return v > 0.f ? v : 0.2f * v; }
__device__ __forceinline__ float elu(float v)   { return v > 0.f ? v : (expf(v) - 1.f); }

// 16B vector reduction (sm_90+): 4x fewer L2 red ops than scalar atomicAdd.
__device__ __forceinline__ void red4(float* addr, float a, float b, float c, float d) {
    asm volatile("red.global.add.v4.f32 [%0], {%1,%2,%3,%4};"
                 :: "l"(addr), "f"(a), "f"(b), "f"(c), "f"(d) : "memory");
}

// ---------------------------------------------------------------------------
// Precompute combined encoder*decoder weight (no nonlinearity between them).
// grid = 129 blocks x 128 threads. Block 128 computes the combined bias.
// ---------------------------------------------------------------------------
__global__ void k_prep(const float* __restrict__ We, const float* __restrict__ Wd,
                       const float* __restrict__ be, const float* __restrict__ bd) {
    int r = blockIdx.x;
    int j = threadIdx.x;
    if (r < 128) {
        float a = 0.f;
        #pragma unroll
        for (int k = 0; k < 64; k++) a += We[r * 64 + k] * Wd[k * 128 + j];
        g_Wcd[r * 128 + j] = a;
    } else {
        float a = bd[j];
        #pragma unroll
        for (int k = 0; k < 64; k++) a += be[k] * Wd[k * 128 + j];
        g_bcd[j] = a;
    }
}

// ---------------------------------------------------------------------------
// h = x @ W_gat ; per-node attention logits ; self-loop init of denom/agg.
// 64-row tile, 256 threads, W (64KB) + x tile (32KB) in smem.
// Thread (tx,ty): rows ty*8..ty*8+7, cols tx*4..tx*4+3 (all in head tx>>3).
// ---------------------------------------------------------------------------
__global__ __launch_bounds__(256) void k1_gat(
    const float* __restrict__ x, const float* __restrict__ Wg,
    const float* __restrict__ att_src, const float* __restrict__ att_dst, int N) {
    extern __shared__ float sm[];
    float* Ws = sm;            // 128*128
    float* xs = sm + 16384;    // 64*128
    int tid = threadIdx.x;

    const float4* Wg4 = (const float4*)Wg;
    float4* Ws4 = (float4*)Ws;
    #pragma unroll 4
    for (int i = tid; i < 4096; i += 256) Ws4[i] = Wg4[i];

    int row0 = blockIdx.x * TM;
    const float4* x4 = (const float4*)x;
    float4* xs4 = (float4*)xs;
    for (int i = tid; i < TM * 32; i += 256) {
        int r = i >> 5;
        int gr = row0 + r;
        xs4[i] = (gr < N) ? x4[(size_t)gr * 32 + (i & 31)] : make_float4(0.f, 0.f, 0.f, 0.f);
    }
    __syncthreads();

    int tx = tid & 31, ty = tid >> 5;
    float acc[8][4];
    #pragma unroll
    for (int i = 0; i < 8; i++)
        #pragma unroll
        for (int j = 0; j < 4; j++) acc[i][j] = 0.f;

    for (int k = 0; k < 128; k += 4) {
        float4 w0 = *(float4*)&Ws[(k + 0) * 128 + tx * 4];
        float4 w1 = *(float4*)&Ws[(k + 1) * 128 + tx * 4];
        float4 w2 = *(float4*)&Ws[(k + 2) * 128 + tx * 4];
        float4 w3 = *(float4*)&Ws[(k + 3) * 128 + tx * 4];
        #pragma unroll
        for (int i = 0; i < 8; i++) {
            float4 xv = *(float4*)&xs[(ty * 8 + i) * 128 + k];
            acc[i][0] += xv.x * w0.x + xv.y * w1.x + xv.z * w2.x + xv.w * w3.x;
            acc[i][1] += xv.x * w0.y + xv.y * w1.y + xv.z * w2.y + xv.w * w3.y;
            acc[i][2] += xv.x * w0.z + xv.y * w1.z + xv.z * w2.z + xv.w * w3.z;
            acc[i][3] += xv.x * w0.w + xv.y * w1.w + xv.z * w2.w + xv.w * w3.w;
        }
    }

    // att_src/att_dst are [4,32] = 128 floats; this thread's 4 cols = float4 [tx].
    float4 at_s = ((const float4*)att_src)[tx];
    float4 at_d = ((const float4*)att_dst)[tx];
    int hh = tx >> 3;

    #pragma unroll
    for (int i = 0; i < 8; i++) {
        float as_p = acc[i][0] * at_s.x + acc[i][1] * at_s.y + acc[i][2] * at_s.z + acc[i][3] * at_s.w;
        float ad_p = acc[i][0] * at_d.x + acc[i][1] * at_d.y + acc[i][2] * at_d.z + acc[i][3] * at_d.w;
        #pragma unroll
        for (int off = 4; off >= 1; off >>= 1) {
            as_p += __shfl_xor_sync(0xffffffffu, as_p, off);
            ad_p += __shfl_xor_sync(0xffffffffu, ad_p, off);
        }
        float asum = as_p + ad_p;                 // self-loop logit
        float p = expf(lrelu(asum));              // self-loop exp term
        int gr = row0 + ty * 8 + i;
        if (gr < N) {
            float4 hv = make_float4(acc[i][0], acc[i][1], acc[i][2], acc[i][3]);
            ((float4*)g_h)[(size_t)gr * 32 + tx] = hv;
            ((float4*)g_agg)[(size_t)gr * 32 + tx] =
                make_float4(p * hv.x, p * hv.y, p * hv.z, p * hv.w);
            if ((tx & 7) == 0) {
                g_asrc[gr * 4 + hh] = as_p;
                g_adst[gr * 4 + hh] = ad_p;
                g_denom[gr * 4 + hh] = p;
            }
        }
    }
}

// ---------------------------------------------------------------------------
// One warp per edge: coalesced 512B read of h[src], vector reductions to dst.
// edge_index read as int32 (JAX default integer width on device).
// ---------------------------------------------------------------------------
__global__ __launch_bounds__(256) void k_edge(const int* __restrict__ ei, int E) {
    int e = blockIdx.x * 8 + (threadIdx.x >> 5);
    if (e >= E) return;
    int lane = threadIdx.x & 31;
    int s = ei[e];
    int d = ei[E + e];

    float4 as = ((const float4*)g_asrc)[s];
    float4 ad = ((const float4*)g_adst)[d];
    // this lane's head = lane>>3
    float asv = lane < 16 ? (lane < 8 ? as.x : as.y) : (lane < 24 ? as.z : as.w);
    float adv = lane < 16 ? (lane < 8 ? ad.x : ad.y) : (lane < 24 ? ad.z : ad.w);
    float ev = asv + adv;
    float p = expf(ev > 0.f ? ev : 0.2f * ev);

    float p1 = __shfl_sync(0xffffffffu, p, 8);
    float p2 = __shfl_sync(0xffffffffu, p, 16);
    float p3 = __shfl_sync(0xffffffffu, p, 24);
    if (lane == 0) red4(&g_denom[(size_t)d * 4], p, p1, p2, p3);

    float4 hv = ((const float4*)g_h)[(size_t)s * 32 + lane];
    red4(&g_agg[(size_t)d * 128 + lane * 4], p * hv.x, p * hv.y, p * hv.z, p * hv.w);
}

// ---------------------------------------------------------------------------
// x1 = elu(agg/denom + b_gat); dec = x1@W_cd + b_cd; x2 = elu(dec);
// out = x2@W_out + b_out.  Both 128x128 weights live in smem (128KB) +
// a 64x128 activation tile reused between the two GEMMs.
// ---------------------------------------------------------------------------
__global__ __launch_bounds__(256) void k_tail(
    const float* __restrict__ b_gat, const float* __restrict__ Wo_g,
    const float* __restrict__ b_out, float* __restrict__ out, int N) {
    extern __shared__ float sm[];
    float* Wc = sm;            // 128*128
    float* Wo = sm + 16384;    // 128*128
    float* t  = sm + 32768;    // 64*128 activation tile
    int tid = threadIdx.x;

    float4* Wc4 = (float4*)Wc;
    float4* Wo4 = (float4*)Wo;
    const float4* gW = (const float4*)g_Wcd;
    const float4* oW = (const float4*)Wo_g;
    #pragma unroll 4
    for (int i = tid; i < 4096; i += 256) { Wc4[i] = gW[i]; Wo4[i] = oW[i]; }

    int row0 = blockIdx.x * TM;
    const float4* agg4 = (const float4*)g_agg;
    const float4* bg4 = (const float4*)b_gat;
    float4* t4 = (float4*)t;
    for (int i = tid; i < TM * 32; i += 256) {
        int r = i >> 5;
        int gr = row0 + r;
        int c4 = i & 31;
        float4 v = make_float4(0.f, 0.f, 0.f, 0.f);
        if (gr < N) {
            float4 a = agg4[(size_t)gr * 32 + c4];
            float inv = 1.f / (g_denom[gr * 4 + (c4 >> 3)] + 1e-16f);
            float4 bg = bg4[c4];
            v.x = elu(a.x * inv + bg.x);
            v.y = elu(a.y * inv + bg.y);
            v.z = elu(a.z * inv + bg.z);
            v.w = elu(a.w * inv + bg.w);
        }
        t4[i] = v;
    }
    __syncthreads();

    int tx = tid & 31, ty = tid >> 5;
    float acc[8][4];

    // GEMM 1: t(x1) @ Wc
    #pragma unroll
    for (int i = 0; i < 8; i++)
        #pragma unroll
        for (int j = 0; j < 4; j++) acc[i][j] = 0.f;
    for (int k = 0; k < 128; k += 4) {
        float4 w0 = *(float4*)&Wc[(k + 0) * 128 + tx * 4];
        float4 w1 = *(float4*)&Wc[(k + 1) * 128 + tx * 4];
        float4 w2 = *(float4*)&Wc[(k + 2) * 128 + tx * 4];
        float4 w3 = *(float4*)&Wc[(k + 3) * 128 + tx * 4];
        #pragma unroll
        for (int i = 0; i < 8; i++) {
            float4 xv = *(float4*)&t[(ty * 8 + i) * 128 + k];
            acc[i][0] += xv.x * w0.x + xv.y * w1.x + xv.z * w2.x + xv.w * w3.x;
            acc[i][1] += xv.x * w0.y + xv.y * w1.y + xv.z * w2.y + xv.w * w3.y;
            acc[i][2] += xv.x * w0.z + xv.y * w1.z + xv.z * w2.z + xv.w * w3.z;
            acc[i][3] += xv.x * w0.w + xv.y * w1.w + xv.z * w2.w + xv.w * w3.w;
        }
    }
    float4 bc = ((const float4*)g_bcd)[tx];
    #pragma unroll
    for (int i = 0; i < 8; i++) {
        acc[i][0] = elu(acc[i][0] + bc.x);
        acc[i][1] = elu(acc[i][1] + bc.y);
        acc[i][2] = elu(acc[i][2] + bc.z);
        acc[i][3] = elu(acc[i][3] + bc.w);
    }
    __syncthreads();   // all reads of t done
    #pragma unroll
    for (int i = 0; i < 8; i++)
        *(float4*)&t[(ty * 8 + i) * 128 + tx * 4] =
            make_float4(acc[i][0], acc[i][1], acc[i][2], acc[i][3]);
    __syncthreads();

    // GEMM 2: t(x2) @ Wo
    #pragma unroll
    for (int i = 0; i < 8; i++)
        #pragma unroll
        for (int j = 0; j < 4; j++) acc[i][j] = 0.f;
    for (int k = 0; k < 128; k += 4) {
        float4 w0 = *(float4*)&Wo[(k + 0) * 128 + tx * 4];
        float4 w1 = *(float4*)&Wo[(k + 1) * 128 + tx * 4];
        float4 w2 = *(float4*)&Wo[(k + 2) * 128 + tx * 4];
        float4 w3 = *(float4*)&Wo[(k + 3) * 128 + tx * 4];
        #pragma unroll
        for (int i = 0; i < 8; i++) {
            float4 xv = *(float4*)&t[(ty * 8 + i) * 128 + k];
            acc[i][0] += xv.x * w0.x + xv.y * w1.x + xv.z * w2.x + xv.w * w3.x;
            acc[i][1] += xv.x * w0.y + xv.y * w1.y + xv.z * w2.y + xv.w * w3.y;
            acc[i][2] += xv.x * w0.z + xv.y * w1.z + xv.z * w2.z + xv.w * w3.z;
            acc[i][3] += xv.x * w0.w + xv.y * w1.w + xv.z * w2.w + xv.w * w3.w;
        }
    }
    float4 bo = ((const float4*)b_out)[tx];
    #pragma unroll
    for (int i = 0; i < 8; i++) {
        int gr = row0 + ty * 8 + i;
        if (gr < N) {
            ((float4*)out)[(size_t)gr * 32 + tx] =
                make_float4(acc[i][0] + bo.x, acc[i][1] + bo.y,
                            acc[i][2] + bo.z, acc[i][3] + bo.w);
        }
    }
}

// ---------------------------------------------------------------------------

extern "C" void kernel_launch(void* const* d_in, const int* in_sizes, int n_in,
                              void* d_out, int out_size) {
    const float* x     = (const float*)d_in[0];
    const int*   ei    = (const int*)d_in[1];
    const float* Wg    = (const float*)d_in[2];
    const float* bg    = (const float*)d_in[3];
    const float* att_s = (const float*)d_in[4];
    const float* att_d = (const float*)d_in[5];
    const float* We    = (const float*)d_in[6];
    const float* be    = (const float*)d_in[7];
    const float* Wd    = (const float*)d_in[8];
    const float* bd    = (const float*)d_in[9];
    const float* Wo    = (const float*)d_in[10];
    const float* bo    = (const float*)d_in[11];
    float* out = (float*)d_out;

    int N = in_sizes[0] / 128;
    int E = in_sizes[1] / 2;

    const int SMEM1 = (16384 + 8192) * 4;           // 96 KB
    const int SMEM2 = (16384 * 2 + 8192) * 4;       // 160 KB
    cudaFuncSetAttribute(k1_gat, cudaFuncAttributeMaxDynamicSharedMemorySize, SMEM1);
    cudaFuncSetAttribute(k_tail, cudaFuncAttributeMaxDynamicSharedMemorySize, SMEM2);

    int nb = (N + TM - 1) / TM;

    k_prep<<<129, 128>>>(We, Wd, be, bd);
    k1_gat<<<nb, 256, SMEM1>>>(x, Wg, att_s, att_d, N);
    k_edge<<<(E + 7) / 8, 256>>>(ei, E);
    k_tail<<<nb, 256, SMEM2>>>(bg, Wo, bo, out, N);
}

// round 3
// speedup vs baseline: 1.0440x; 1.0440x over previous
#include <cuda_runtime.h>
#include <math.h>

// ---------------------------------------------------------------------------
// GAT (4 heads x 32) + linear autoencoder head, N=50000, E=800000, C=128.
//   k_prep : W_cd = W_enc @ W_dec (no nonlinearity between), combined bias
//   k1_gat : h = x @ W_gat ; logits ; self-loop init of denom/agg   (GEMM)
//   k_edge : single pass: p=exp(lrelu(a_s[s]+a_d[d])); red.v4 into denom/agg
//   k_tail : x1=elu(agg/denom+b); x2=elu(x1@Wcd+bcd); out=x2@Wo+bo  (2 GEMMs)
// R3: TM 64->128, 256->512 threads/CTA => 16 warps/SM (was 8). k_tail/k1_gat
// were occupancy-bound (issue 54%, fma 38%); this feeds the FMA pipe.
// ---------------------------------------------------------------------------

#define MAXN 50176
#define TM 128

__device__ __align__(16) float g_h[MAXN * 128];
__device__ __align__(16) float g_agg[MAXN * 128];
__device__ __align__(16) float g_asrc[MAXN * 4];
__device__ __align__(16) float g_adst[MAXN * 4];
__device__ __align__(16) float g_denom[MAXN * 4];
__device__ __align__(16) float g_Wcd[128 * 128];
__device__ __align__(16) float g_bcd[128];

__device__ __forceinline__ float lrelu(float v) { return v > 0.f ? v : 0.2f * v; }
__device__ __forceinline__ float elu(float v)   { return v > 0.f ? v : (expf(v) - 1.f); }

__device__ __forceinline__ void red4(float* addr, float a, float b, float c, float d) {
    asm volatile("red.global.add.v4.f32 [%0], {%1,%2,%3,%4};"
                 :: "l"(addr), "f"(a), "f"(b), "f"(c), "f"(d) : "memory");
}

// ---------------------------------------------------------------------------
__global__ void k_prep(const float* __restrict__ We, const float* __restrict__ Wd,
                       const float* __restrict__ be, const float* __restrict__ bd) {
    int r = blockIdx.x;
    int j = threadIdx.x;
    if (r < 128) {
        float a = 0.f;
        #pragma unroll
        for (int k = 0; k < 64; k++) a += We[r * 64 + k] * Wd[k * 128 + j];
        g_Wcd[r * 128 + j] = a;
    } else {
        float a = bd[j];
        #pragma unroll
        for (int k = 0; k < 64; k++) a += be[k] * Wd[k * 128 + j];
        g_bcd[j] = a;
    }
}

// ---------------------------------------------------------------------------
// h = x @ W_gat ; logits ; self-loop init.  128-row tile, 512 threads.
// Thread (tx,ty): rows ty*8..+7 (ty in [0,16)), cols tx*4..+3.
// smem: W 64KB + x tile 64KB = 128KB.
// ---------------------------------------------------------------------------
__global__ __launch_bounds__(512) void k1_gat(
    const float* __restrict__ x, const float* __restrict__ Wg,
    const float* __restrict__ att_src, const float* __restrict__ att_dst, int N) {
    extern __shared__ float sm[];
    float* Ws = sm;            // 128*128
    float* xs = sm + 16384;    // 128*128
    int tid = threadIdx.x;

    const float4* Wg4 = (const float4*)Wg;
    float4* Ws4 = (float4*)Ws;
    #pragma unroll 4
    for (int i = tid; i < 4096; i += 512) Ws4[i] = Wg4[i];

    int row0 = blockIdx.x * TM;
    const float4* x4 = (const float4*)x;
    float4* xs4 = (float4*)xs;
    for (int i = tid; i < TM * 32; i += 512) {
        int r = i >> 5;
        int gr = row0 + r;
        xs4[i] = (gr < N) ? x4[(size_t)gr * 32 + (i & 31)] : make_float4(0.f, 0.f, 0.f, 0.f);
    }
    __syncthreads();

    int tx = tid & 31, ty = tid >> 5;
    float acc[8][4];
    #pragma unroll
    for (int i = 0; i < 8; i++)
        #pragma unroll
        for (int j = 0; j < 4; j++) acc[i][j] = 0.f;

    for (int k = 0; k < 128; k += 4) {
        float4 w0 = *(float4*)&Ws[(k + 0) * 128 + tx * 4];
        float4 w1 = *(float4*)&Ws[(k + 1) * 128 + tx * 4];
        float4 w2 = *(float4*)&Ws[(k + 2) * 128 + tx * 4];
        float4 w3 = *(float4*)&Ws[(k + 3) * 128 + tx * 4];
        #pragma unroll
        for (int i = 0; i < 8; i++) {
            float4 xv = *(float4*)&xs[(ty * 8 + i) * 128 + k];
            acc[i][0] += xv.x * w0.x + xv.y * w1.x + xv.z * w2.x + xv.w * w3.x;
            acc[i][1] += xv.x * w0.y + xv.y * w1.y + xv.z * w2.y + xv.w * w3.y;
            acc[i][2] += xv.x * w0.z + xv.y * w1.z + xv.z * w2.z + xv.w * w3.z;
            acc[i][3] += xv.x * w0.w + xv.y * w1.w + xv.z * w2.w + xv.w * w3.w;
        }
    }

    float4 at_s = ((const float4*)att_src)[tx];
    float4 at_d = ((const float4*)att_dst)[tx];
    int hh = tx >> 3;

    #pragma unroll
    for (int i = 0; i < 8; i++) {
        float as_p = acc[i][0] * at_s.x + acc[i][1] * at_s.y + acc[i][2] * at_s.z + acc[i][3] * at_s.w;
        float ad_p = acc[i][0] * at_d.x + acc[i][1] * at_d.y + acc[i][2] * at_d.z + acc[i][3] * at_d.w;
        #pragma unroll
        for (int off = 4; off >= 1; off >>= 1) {
            as_p += __shfl_xor_sync(0xffffffffu, as_p, off);
            ad_p += __shfl_xor_sync(0xffffffffu, ad_p, off);
        }
        float asum = as_p + ad_p;
        float p = expf(lrelu(asum));
        int gr = row0 + ty * 8 + i;
        if (gr < N) {
            float4 hv = make_float4(acc[i][0], acc[i][1], acc[i][2], acc[i][3]);
            ((float4*)g_h)[(size_t)gr * 32 + tx] = hv;
            ((float4*)g_agg)[(size_t)gr * 32 + tx] =
                make_float4(p * hv.x, p * hv.y, p * hv.z, p * hv.w);
            if ((tx & 7) == 0) {
                g_asrc[gr * 4 + hh] = as_p;
                g_adst[gr * 4 + hh] = ad_p;
                g_denom[gr * 4 + hh] = p;
            }
        }
    }
}

// ---------------------------------------------------------------------------
// One warp per edge: coalesced 512B read of h[src], vector reductions to dst.
// ---------------------------------------------------------------------------
__global__ __launch_bounds__(256) void k_edge(const int* __restrict__ ei, int E) {
    int e = blockIdx.x * 8 + (threadIdx.x >> 5);
    if (e >= E) return;
    int lane = threadIdx.x & 31;
    int s = ei[e];
    int d = ei[E + e];

    float4 as = ((const float4*)g_asrc)[s];
    float4 ad = ((const float4*)g_adst)[d];
    float asv = lane < 16 ? (lane < 8 ? as.x : as.y) : (lane < 24 ? as.z : as.w);
    float adv = lane < 16 ? (lane < 8 ? ad.x : ad.y) : (lane < 24 ? ad.z : ad.w);
    float ev = asv + adv;
    float p = expf(ev > 0.f ? ev : 0.2f * ev);

    float p1 = __shfl_sync(0xffffffffu, p, 8);
    float p2 = __shfl_sync(0xffffffffu, p, 16);
    float p3 = __shfl_sync(0xffffffffu, p, 24);
    if (lane == 0) red4(&g_denom[(size_t)d * 4], p, p1, p2, p3);

    float4 hv = ((const float4*)g_h)[(size_t)s * 32 + lane];
    red4(&g_agg[(size_t)d * 128 + lane * 4], p * hv.x, p * hv.y, p * hv.z, p * hv.w);
}

// ---------------------------------------------------------------------------
// x1=elu(agg/denom+b_gat); x2=elu(x1@Wcd+bcd); out=x2@Wo+bo.
// 128-row tile, 512 threads. smem: Wc 64K + Wo 64K + t 64K = 192KB.
// ---------------------------------------------------------------------------
__global__ __launch_bounds__(512) void k_tail(
    const float* __restrict__ b_gat, const float* __restrict__ Wo_g,
    const float* __restrict__ b_out, float* __restrict__ out, int N) {
    extern __shared__ float sm[];
    float* Wc = sm;            // 128*128
    float* Wo = sm + 16384;    // 128*128
    float* t  = sm + 32768;    // 128*128 activation tile
    int tid = threadIdx.x;

    float4* Wc4 = (float4*)Wc;
    float4* Wo4 = (float4*)Wo;
    const float4* gW = (const float4*)g_Wcd;
    const float4* oW = (const float4*)Wo_g;
    #pragma unroll 4
    for (int i = tid; i < 4096; i += 512) { Wc4[i] = gW[i]; Wo4[i] = oW[i]; }

    int row0 = blockIdx.x * TM;
    const float4* agg4 = (const float4*)g_agg;
    const float4* bg4 = (const float4*)b_gat;
    float4* t4 = (float4*)t;
    for (int i = tid; i < TM * 32; i += 512) {
        int r = i >> 5;
        int gr = row0 + r;
        int c4 = i & 31;
        float4 v = make_float4(0.f, 0.f, 0.f, 0.f);
        if (gr < N) {
            float4 a = agg4[(size_t)gr * 32 + c4];
            float inv = 1.f / (g_denom[gr * 4 + (c4 >> 3)] + 1e-16f);
            float4 bg = bg4[c4];
            v.x = elu(a.x * inv + bg.x);
            v.y = elu(a.y * inv + bg.y);
            v.z = elu(a.z * inv + bg.z);
            v.w = elu(a.w * inv + bg.w);
        }
        t4[i] = v;
    }
    __syncthreads();

    int tx = tid & 31, ty = tid >> 5;
    float acc[8][4];

    // GEMM 1: t(x1) @ Wc
    #pragma unroll
    for (int i = 0; i < 8; i++)
        #pragma unroll
        for (int j = 0; j < 4; j++) acc[i][j] = 0.f;
    for (int k = 0; k < 128; k += 4) {
        float4 w0 = *(float4*)&Wc[(k + 0) * 128 + tx * 4];
        float4 w1 = *(float4*)&Wc[(k + 1) * 128 + tx * 4];
        float4 w2 = *(float4*)&Wc[(k + 2) * 128 + tx * 4];
        float4 w3 = *(float4*)&Wc[(k + 3) * 128 + tx * 4];
        #pragma unroll
        for (int i = 0; i < 8; i++) {
            float4 xv = *(float4*)&t[(ty * 8 + i) * 128 + k];
            acc[i][0] += xv.x * w0.x + xv.y * w1.x + xv.z * w2.x + xv.w * w3.x;
            acc[i][1] += xv.x * w0.y + xv.y * w1.y + xv.z * w2.y + xv.w * w3.y;
            acc[i][2] += xv.x * w0.z + xv.y * w1.z + xv.z * w2.z + xv.w * w3.z;
            acc[i][3] += xv.x * w0.w + xv.y * w1.w + xv.z * w2.w + xv.w * w3.w;
        }
    }
    float4 bc = ((const float4*)g_bcd)[tx];
    #pragma unroll
    for (int i = 0; i < 8; i++) {
        acc[i][0] = elu(acc[i][0] + bc.x);
        acc[i][1] = elu(acc[i][1] + bc.y);
        acc[i][2] = elu(acc[i][2] + bc.z);
        acc[i][3] = elu(acc[i][3] + bc.w);
    }
    __syncthreads();
    #pragma unroll
    for (int i = 0; i < 8; i++)
        *(float4*)&t[(ty * 8 + i) * 128 + tx * 4] =
            make_float4(acc[i][0], acc[i][1], acc[i][2], acc[i][3]);
    __syncthreads();

    // GEMM 2: t(x2) @ Wo
    #pragma unroll
    for (int i = 0; i < 8; i++)
        #pragma unroll
        for (int j = 0; j < 4; j++) acc[i][j] = 0.f;
    for (int k = 0; k < 128; k += 4) {
        float4 w0 = *(float4*)&Wo[(k + 0) * 128 + tx * 4];
        float4 w1 = *(float4*)&Wo[(k + 1) * 128 + tx * 4];
        float4 w2 = *(float4*)&Wo[(k + 2) * 128 + tx * 4];
        float4 w3 = *(float4*)&Wo[(k + 3) * 128 + tx * 4];
        #pragma unroll
        for (int i = 0; i < 8; i++) {
            float4 xv = *(float4*)&t[(ty * 8 + i) * 128 + k];
            acc[i][0] += xv.x * w0.x + xv.y * w1.x + xv.z * w2.x + xv.w * w3.x;
            acc[i][1] += xv.x * w0.y + xv.y * w1.y + xv.z * w2.y + xv.w * w3.y;
            acc[i][2] += xv.x * w0.z + xv.y * w1.z + xv.z * w2.z + xv.w * w3.z;
            acc[i][3] += xv.x * w0.w + xv.y * w1.w + xv.z * w2.w + xv.w * w3.w;
        }
    }
    float4 bo = ((const float4*)b_out)[tx];
    #pragma unroll
    for (int i = 0; i < 8; i++) {
        int gr = row0 + ty * 8 + i;
        if (gr < N) {
            ((float4*)out)[(size_t)gr * 32 + tx] =
                make_float4(acc[i][0] + bo.x, acc[i][1] + bo.y,
                            acc[i][2] + bo.z, acc[i][3] + bo.w);
        }
    }
}

// ---------------------------------------------------------------------------

extern "C" void kernel_launch(void* const* d_in, const int* in_sizes, int n_in,
                              void* d_out, int out_size) {
    const float* x     = (const float*)d_in[0];
    const int*   ei    = (const int*)d_in[1];
    const float* Wg    = (const float*)d_in[2];
    const float* bg    = (const float*)d_in[3];
    const float* att_s = (const float*)d_in[4];
    const float* att_d = (const float*)d_in[5];
    const float* We    = (const float*)d_in[6];
    const float* be    = (const float*)d_in[7];
    const float* Wd    = (const float*)d_in[8];
    const float* bd    = (const float*)d_in[9];
    const float* Wo    = (const float*)d_in[10];
    const float* bo    = (const float*)d_in[11];
    float* out = (float*)d_out;

    int N = in_sizes[0] / 128;
    int E = in_sizes[1] / 2;

    const int SMEM1 = (16384 + 16384) * 4;            // 128 KB
    const int SMEM2 = (16384 * 2 + 16384) * 4;        // 192 KB
    cudaFuncSetAttribute(k1_gat, cudaFuncAttributeMaxDynamicSharedMemorySize, SMEM1);
    cudaFuncSetAttribute(k_tail, cudaFuncAttributeMaxDynamicSharedMemorySize, SMEM2);

    int nb = (N + TM - 1) / TM;

    k_prep<<<129, 128>>>(We, Wd, be, bd);
    k1_gat<<<nb, 512, SMEM1>>>(x, Wg, att_s, att_d, N);
    k_edge<<<(E + 7) / 8, 256>>>(ei, E);
    k_tail<<<nb, 512, SMEM2>>>(bg, Wo, bo, out, N);
}